// round 16
// baseline (speedup 1.0000x reference)
#include <cuda_runtime.h>
#include <cstdint>

#define Bsz 2048
#define Tsz 512
#define Asz 32
#define Hsz 16
#define CH 16
#define NCHUNK (Tsz / CH)

typedef unsigned long long u64;
typedef unsigned int u32;

__device__ __forceinline__ u64 pack2(float lo, float hi) {
    u64 r; asm("mov.b64 %0, {%1, %2};" : "=l"(r) : "f"(lo), "f"(hi)); return r;
}
__device__ __forceinline__ void unpack2(u64 v, float& lo, float& hi) {
    asm("mov.b64 {%0, %1}, %2;" : "=f"(lo), "=f"(hi) : "l"(v));
}
__device__ __forceinline__ u64 fma2(u64 a, u64 b, u64 c) {
    u64 d; asm("fma.rn.f32x2 %0, %1, %2, %3;" : "=l"(d) : "l"(a), "l"(b), "l"(c)); return d;
}
__device__ __forceinline__ u64 add2(u64 a, u64 b) {
    u64 d; asm("add.rn.f32x2 %0, %1, %2;" : "=l"(d) : "l"(a), "l"(b)); return d;
}
__device__ __forceinline__ float hsum2(u64 v) {
    float lo, hi; unpack2(v, lo, hi); return lo + hi;
}
__device__ __forceinline__ float tanh_fast(float x) {
    float y; asm("tanh.approx.f32 %0, %1;" : "=f"(y) : "f"(x)); return y;
}
__device__ __forceinline__ float sigmoid_fast(float x) {
    return fmaf(0.5f, tanh_fast(0.5f * x), 0.5f);
}
__device__ __forceinline__ u32 smaddr(const void* p) {
    return (u32)__cvta_generic_to_shared(p);
}
__device__ __forceinline__ void cp16(u32 s, const void* g) {
    asm volatile("cp.async.ca.shared.global [%0], [%1], 16;" :: "r"(s), "l"(g));
}
#define CP_COMMIT() asm volatile("cp.async.commit_group;" ::: "memory")
#define CP_WAIT1()  asm volatile("cp.async.wait_group 1;" ::: "memory")

// ============================================================================
// MONOLITHIC INDEPENDENT WARPS: one warp = one batch element does everything.
//   - x streamed via its OWN cp.async double buffer (per-warp, syncwarp only)
//   - x-projection computed inline per step (no pg buffer, no CTA barrier)
//   - recurrence: lo/hi gate split (lane j: i_j,g_j; lane 16+j: f_j,o_j),
//     tanh.approx activations
//   - actor head fused into the step (reuses hv registers)
//   - critic one chunk behind from the warp's own 32-deep h ring
// ZERO __syncthreads in the loop -> no inter-warp coupling; warps on an SMSP
// hide each other's latency freely. 170-reg cap (3 CTAs/SM), grid 512.
// ============================================================================
__global__ void __launch_bounds__(128, 3) lstm_mono(
    const float* __restrict__ xin, const float* __restrict__ masks,
    const float* __restrict__ h0, const float* __restrict__ c0,
    const float* __restrict__ w_ih, const float* __restrict__ w_hh,
    const float* __restrict__ b_ih, const float* __restrict__ b_hh,
    const float* __restrict__ w_actor, const float* __restrict__ b_actor,
    const float* __restrict__ w_critic, const float* __restrict__ b_critic,
    float* __restrict__ actor, float* __restrict__ critic,
    float* __restrict__ hT, float* __restrict__ cT)
{
    __shared__ __align__(16) float xsm[4][2][CH * 32];  // 16KB (per-warp bufs)
    __shared__ __align__(16) float hbuf[4][32][16];     // 8KB  (per-warp rings)
    __shared__ __align__(16) float wc_s[16];

    const int tid  = threadIdx.x;
    const int w    = tid >> 5;
    const int lane = tid & 31;
    const int j    = lane & 15;
    const bool hi_half = lane >= 16;
    const int b    = blockIdx.x * 4 + w;

    if (tid < 16) wc_s[tid] = w_critic[tid];

    // ---- weights in registers (lo/hi split keeps this at ~112 regs)
    u64 wA[16], wB[16];                  // w_ih rows lane, 32+lane
    {
        const u64* pA = (const u64*)(w_ih + lane * 32);
        const u64* pB = (const u64*)(w_ih + (32 + lane) * 32);
#pragma unroll
        for (int k = 0; k < 16; k++) { wA[k] = pA[k]; wB[k] = pB[k]; }
    }
    u64 whP[8], whQ[8];                  // w_hh rows lane, 32+lane
    {
        const u64* pP = (const u64*)(w_hh + lane * 16);
        const u64* pQ = (const u64*)(w_hh + (32 + lane) * 16);
#pragma unroll
        for (int k = 0; k < 8; k++) { whP[k] = pP[k]; whQ[k] = pQ[k]; }
    }
    u64 wa[8];                           // actor row = lane
    {
        const u64* pa = (const u64*)(w_actor + lane * 16);
#pragma unroll
        for (int k = 0; k < 8; k++) wa[k] = pa[k];
    }
    const u64 biasA2 = pack2(b_ih[lane] + b_hh[lane], 0.0f);
    const u64 biasB2 = pack2(b_ih[32 + lane] + b_hh[32 + lane], 0.0f);
    const float bact = b_actor[lane];
    const float bcr  = b_critic[0];

    const float* xb = xin + (size_t)b * Tsz * Asz;
    const float* mb = masks + (size_t)b * Tsz;
    float* actb     = actor + (size_t)b * Tsz * Asz;
    float* crb      = critic + (size_t)b * Tsz;

    float c = c0[b * Hsz + j];
    if (lane < 16) hbuf[w][31][lane] = h0[b * Hsz + lane];   // h_{-1}
    float h2 = 0.0f;

    __syncthreads();                     // wc_s visible (once, outside loop)

    auto loadx = [&](int ch) {           // 16 steps = 512 floats = 2KB
        const int bf = ch & 1;
        u32 dst = smaddr(&xsm[w][bf][0]);
        const float* src = xb + ch * (CH * 32);
#pragma unroll
        for (int q = 0; q < 4; q++)
            cp16(dst + lane * 16 + q * 512, src + lane * 4 + q * 128);
    };
    auto critic_pass = [&](int cc) {     // chunk cc: h final in OWN ring
        if (lane < 16) {                 // lane = step within chunk
            const int t = cc * CH + lane;
            const u64* hp = (const u64*)&hbuf[w][t & 31][0];
            const u64* wc = (const u64*)wc_s;
            u64 a0 = 0, a1 = 0;
#pragma unroll
            for (int k = 0; k < 4; k++) {
                a0 = fma2(wc[2 * k],     hp[2 * k],     a0);
                a1 = fma2(wc[2 * k + 1], hp[2 * k + 1], a1);
            }
            crb[t] = hsum2(add2(a0, a1)) + bcr;
        }
    };

    loadx(0); CP_COMMIT();
    loadx(1); CP_COMMIT();
    CP_WAIT1();                          // x chunk 0 landed
    __syncwarp();

    float4 mv4 = make_float4(0.f, 0.f, 0.f, 0.f);

    for (int cc = 0; cc < NCHUNK; cc++) {
        if (cc >= 1) critic_pass(cc - 1);
#pragma unroll
        for (int s = 0; s < CH; s++) {
            const int t = cc * CH + s;
            if ((s & 3) == 0) mv4 = *(const float4*)&mb[t];
            const float m = (s & 3) == 0 ? mv4.x
                          : (s & 3) == 1 ? mv4.y
                          : (s & 3) == 2 ? mv4.z : mv4.w;
            const float cm = c * m;

            // ---- x projection (inline, broadcast LDS from own buffer)
            const ulonglong2* xp = (const ulonglong2*)&xsm[w][cc & 1][s * 32];
            u64 xa0 = biasA2, xa1 = 0, xb0 = biasB2, xb1 = 0;
#pragma unroll
            for (int q = 0; q < 8; q++) {
                const ulonglong2 v = xp[q];
                xa0 = fma2(wA[2 * q],     v.x, xa0);
                xa1 = fma2(wA[2 * q + 1], v.y, xa1);
                xb0 = fma2(wB[2 * q],     v.x, xb0);
                xb1 = fma2(wB[2 * q + 1], v.y, xb1);
            }
            const float xP = hsum2(add2(xa0, xa1));   // lo: pre-i, hi: pre-f
            const float xQ = hsum2(add2(xb0, xb1));   // lo: pre-g, hi: pre-o

            // ---- h_{t-1} broadcast from own ring
            u64 hv[8];
            {
                const ulonglong2* hp = (const ulonglong2*)&hbuf[w][(t + 31) & 31][0];
#pragma unroll
                for (int q = 0; q < 4; q++) {
                    const ulonglong2 v = hp[q];
                    hv[2 * q] = v.x; hv[2 * q + 1] = v.y;
                }
            }
            // ---- fused actor head for step t-1 (reuses hv)
            {
                u64 A0 = 0, A1 = 0;
#pragma unroll
                for (int k = 0; k < 4; k++) {
                    A0 = fma2(wa[2 * k],     hv[2 * k],     A0);
                    A1 = fma2(wa[2 * k + 1], hv[2 * k + 1], A1);
                }
                const float av = hsum2(add2(A0, A1)) + bact;
                if (t > 0) actb[(t - 1) * Asz + lane] = av;
            }
            // ---- gates
            u64 aP0 = 0, aP1 = 0, aQ0 = 0, aQ1 = 0;
#pragma unroll
            for (int k = 0; k < 4; k++) {
                aP0 = fma2(whP[2 * k],     hv[2 * k],     aP0);
                aP1 = fma2(whP[2 * k + 1], hv[2 * k + 1], aP1);
                aQ0 = fma2(whQ[2 * k],     hv[2 * k],     aQ0);
                aQ1 = fma2(whQ[2 * k + 1], hv[2 * k + 1], aQ1);
            }
            const float gP = fmaf(m, hsum2(add2(aP0, aP1)), xP);  // lo:i hi:f
            const float gQ = fmaf(m, hsum2(add2(aQ0, aQ1)), xQ);  // lo:g hi:o

            const float vP = sigmoid_fast(gP);
            const float tQ = tanh_fast(hi_half ? 0.5f * gQ : gQ);
            const float vQ = hi_half ? fmaf(0.5f, tQ, 0.5f) : tQ;

            const float p  = vP * vQ;                          // lo: i*g
            const float ig = __shfl_sync(0xffffffffu, p, j);   // hi gets i*g

            c  = fmaf(vP, cm, ig);                             // hi lanes
            h2 = vQ * tanh_fast(c);                            // hi lanes

            if (hi_half) hbuf[w][t & 31][j] = h2;
            __syncwarp();
        }
        // prefetch x for chunk cc+2 (buffer cc&1 is now free)
        if (cc + 2 < NCHUNK) loadx(cc + 2);
        CP_COMMIT();
        CP_WAIT1();                       // x chunk cc+1 landed
        __syncwarp();
    }
    critic_pass(NCHUNK - 1);

    // tail: actor for t = Tsz-1
    {
        u64 hv[8];
        const ulonglong2* hp = (const ulonglong2*)&hbuf[w][(Tsz - 1) & 31][0];
#pragma unroll
        for (int q = 0; q < 4; q++) {
            const ulonglong2 v = hp[q];
            hv[2 * q] = v.x; hv[2 * q + 1] = v.y;
        }
        u64 A0 = 0, A1 = 0;
#pragma unroll
        for (int k = 0; k < 4; k++) {
            A0 = fma2(wa[2 * k],     hv[2 * k],     A0);
            A1 = fma2(wa[2 * k + 1], hv[2 * k + 1], A1);
        }
        actb[(Tsz - 1) * Asz + lane] = hsum2(add2(A0, A1)) + bact;
    }

    if (hi_half) {
        hT[b * Hsz + j] = h2;
        cT[b * Hsz + j] = c;
    }
}

extern "C" void kernel_launch(void* const* d_in, const int* in_sizes, int n_in,
                              void* d_out, int out_size) {
    const float* xin      = (const float*)d_in[0];
    const float* masks    = (const float*)d_in[1];
    const float* h0       = (const float*)d_in[2];
    const float* c0       = (const float*)d_in[3];
    const float* w_ih     = (const float*)d_in[4];
    const float* w_hh     = (const float*)d_in[5];
    const float* b_ih     = (const float*)d_in[6];
    const float* b_hh     = (const float*)d_in[7];
    const float* w_actor  = (const float*)d_in[8];
    const float* b_actor  = (const float*)d_in[9];
    const float* w_critic = (const float*)d_in[10];
    const float* b_critic = (const float*)d_in[11];

    float* out    = (float*)d_out;
    float* actor  = out;
    float* critic = actor + (size_t)Bsz * Tsz * Asz;
    float* hT     = critic + (size_t)Bsz * Tsz;
    float* cT     = hT + (size_t)Bsz * Hsz;

    lstm_mono<<<Bsz / 4, 128>>>(xin, masks, h0, c0, w_ih, w_hh, b_ih, b_hh,
                                w_actor, b_actor, w_critic, b_critic,
                                actor, critic, hT, cT);
}

// round 17
// speedup vs baseline: 1.0002x; 1.0002x over previous
#include <cuda_runtime.h>
#include <cstdint>

#define Bsz 2048
#define Tsz 512
#define Asz 32
#define Hsz 16
#define CH 8
#define NCHUNK (Tsz / CH)

typedef unsigned long long u64;
typedef unsigned int u32;

__device__ __forceinline__ void unpack2(u64 v, float& lo, float& hi) {
    asm("mov.b64 {%0, %1}, %2;" : "=f"(lo), "=f"(hi) : "l"(v));
}
__device__ __forceinline__ u64 fma2(u64 a, u64 b, u64 c) {
    u64 d; asm("fma.rn.f32x2 %0, %1, %2, %3;" : "=l"(d) : "l"(a), "l"(b), "l"(c)); return d;
}
__device__ __forceinline__ u64 add2(u64 a, u64 b) {
    u64 d; asm("add.rn.f32x2 %0, %1, %2;" : "=l"(d) : "l"(a), "l"(b)); return d;
}
__device__ __forceinline__ float hsum2(u64 v) {
    float lo, hi; unpack2(v, lo, hi); return lo + hi;
}
__device__ __forceinline__ float tanh_fast(float x) {
    float y; asm("tanh.approx.f32 %0, %1;" : "=f"(y) : "f"(x)); return y;
}
__device__ __forceinline__ float sigmoid_fast(float x) {
    return fmaf(0.5f, tanh_fast(0.5f * x), 0.5f);
}
__device__ __forceinline__ u32 smaddr(const void* p) {
    return (u32)__cvta_generic_to_shared(p);
}
__device__ __forceinline__ void cp16(u32 s, const void* g) {
    asm volatile("cp.async.ca.shared.global [%0], [%1], 16;" :: "r"(s), "l"(g));
}
#define CP_COMMIT() asm volatile("cp.async.commit_group;" ::: "memory")
#define CP_WAIT1()  asm volatile("cp.async.wait_group 1;" ::: "memory")

// ============================================================================
// CTA = 192 threads = 6 warps = 4 batch elements.
//   4 consumer warps (1 elem each): recurrence (lo/hi gate split, tanh.approx)
//     + fused actor head (reuses hv regs) + chunk-behind critic. (R15 proven.)
//   2 producer warps (2 elems each): x pregates one chunk AHEAD. Weights are
//     SHARED across its 2 elements (zero extra regs, fills its idle slots —
//     in R15 producers idled ~50% at every barrier).
// Producer warps sit on SMSPs {0,3} or {1,2} by blockIdx parity (wid%4 mix).
// elems/SM: 12 (3 CTAs) vs R15's 10; waves 1.15 vs 1.38.
// ============================================================================
__global__ void __launch_bounds__(192, 3) lstm_fused(
    const float* __restrict__ xin, const float* __restrict__ masks,
    const float* __restrict__ h0, const float* __restrict__ c0,
    const float* __restrict__ w_ih, const float* __restrict__ w_hh,
    const float* __restrict__ b_ih, const float* __restrict__ b_hh,
    const float* __restrict__ w_actor, const float* __restrict__ b_actor,
    const float* __restrict__ w_critic, const float* __restrict__ b_critic,
    float* __restrict__ actor, float* __restrict__ critic,
    float* __restrict__ hT, float* __restrict__ cT)
{
    __shared__ __align__(16) float pgsm[4][2][CH * 64];  // 16KB
    __shared__ __align__(16) float xsm[4][2][CH * 32];   // 8KB
    __shared__ __align__(16) float hbuf[4][32][16];      // 8KB ring: slot t&31 = h_t
    __shared__ __align__(16) float wc_s[16];

    const int tid  = threadIdx.x;
    const int w    = tid >> 5;
    const int lane = tid & 31;
    const int par  = blockIdx.x & 1;
    // producers on SMSPs {0,3} (par=0) or {1,2} (par=1)
    const bool is_prod = par == 0 ? (w == 0 || w == 3) : (w == 1 || w == 2);
    // role ranks -> element assignment
    int rank;
    if (par == 0) rank = is_prod ? (w == 0 ? 0 : 1)
                                 : (w == 1 ? 0 : w == 2 ? 1 : w == 4 ? 2 : 3);
    else          rank = is_prod ? (w == 1 ? 0 : 1)
                                 : (w == 0 ? 0 : w == 3 ? 1 : w == 4 ? 2 : 3);
    const int b0 = blockIdx.x * 4;

    if (tid < 16) wc_s[tid] = w_critic[tid];

    if (is_prod) {
        // ---------------- PRODUCER: x pregates for 2 elems ----------------
        const int e0 = 2 * rank;
        u64 wA[16], wB[16];                  // shared across both elements
        {
            const u64* pA = (const u64*)(w_ih + lane * 32);
            const u64* pB = (const u64*)(w_ih + (32 + lane) * 32);
#pragma unroll
            for (int k = 0; k < 16; k++) { wA[k] = pA[k]; wB[k] = pB[k]; }
        }
        const float bsA = b_ih[lane] + b_hh[lane];
        const float bsB = b_ih[32 + lane] + b_hh[32 + lane];

        const float* xb0 = xin + (size_t)(b0 + e0) * Tsz * Asz;
        const float* xb1 = xin + (size_t)(b0 + e0 + 1) * Tsz * Asz;

        auto loadx = [&](int ch) {           // CH=8 steps = 256 floats/elem
            const int bf = ch & 1;
            u32 d0 = smaddr(&xsm[e0][bf][0]);
            u32 d1 = smaddr(&xsm[e0 + 1][bf][0]);
            const float* s0 = xb0 + ch * (CH * 32);
            const float* s1 = xb1 + ch * (CH * 32);
            cp16(d0 + lane * 16,       s0 + lane * 4);
            cp16(d0 + lane * 16 + 512, s0 + lane * 4 + 128);
            cp16(d1 + lane * 16,       s1 + lane * 4);
            cp16(d1 + lane * 16 + 512, s1 + lane * 4 + 128);
        };
        auto comp = [&](int ch) {
            const int bf = ch & 1;
#pragma unroll
            for (int ee = 0; ee < 2; ee++) {
#pragma unroll
                for (int s = 0; s < CH; s++) {
                    const ulonglong2* xp = (const ulonglong2*)&xsm[e0 + ee][bf][s * 32];
                    u64 a0 = 0, a1 = 0, g0 = 0, g1 = 0;
#pragma unroll
                    for (int q = 0; q < 8; q++) {
                        const ulonglong2 v = xp[q];
                        a0 = fma2(wA[2 * q],     v.x, a0);
                        a1 = fma2(wA[2 * q + 1], v.y, a1);
                        g0 = fma2(wB[2 * q],     v.x, g0);
                        g1 = fma2(wB[2 * q + 1], v.y, g1);
                    }
                    float2 o;
                    o.x = hsum2(add2(a0, a1)) + bsA;
                    o.y = hsum2(add2(g0, g1)) + bsB;
                    *(float2*)&pgsm[e0 + ee][bf][s * 64 + 2 * lane] = o;
                }
            }
        };

        loadx(0); CP_COMMIT();
        loadx(1); CP_COMMIT();
        CP_WAIT1();
        comp(0);
        __syncthreads();                     // pg chunk 0 ready

        for (int cc = 0; cc < NCHUNK; cc++) {
            if (cc + 2 < NCHUNK) loadx(cc + 2);
            CP_COMMIT();
            CP_WAIT1();                      // x chunk cc+1 landed
            if (cc + 1 < NCHUNK) comp(cc + 1);
            __syncthreads();
        }
    } else {
        // ---------------- CONSUMER: recurrence + fused actor + critic ------
        const int e = rank;
        const int b = b0 + e;
        const int j = lane & 15;
        const bool hi_half = lane >= 16;

        u64 whP[8], whQ[8];                  // w_hh rows lane, 32+lane
        {
            const u64* pP = (const u64*)(w_hh + lane * 16);
            const u64* pQ = (const u64*)(w_hh + (32 + lane) * 16);
#pragma unroll
            for (int k = 0; k < 8; k++) { whP[k] = pP[k]; whQ[k] = pQ[k]; }
        }
        u64 wa[8];                           // actor row = lane
        {
            const u64* pa = (const u64*)(w_actor + lane * 16);
#pragma unroll
            for (int k = 0; k < 8; k++) wa[k] = pa[k];
        }
        const float bact = b_actor[lane];
        const float bcr  = b_critic[0];

        const float* mb = masks + (size_t)b * Tsz;
        float* actb     = actor + (size_t)b * Tsz * Asz;
        float* crb      = critic + (size_t)b * Tsz;

        float c = c0[b * Hsz + j];
        if (lane < 16) hbuf[e][31][lane] = h0[b * Hsz + lane];  // h_{-1}
        float h2 = 0.0f;

        auto critic_pass = [&](int cc) {     // chunk cc: h final in OWN ring
            if (lane < CH) {                 // lane = step within chunk
                const int t = cc * CH + lane;
                const u64* hp = (const u64*)&hbuf[e][t & 31][0];
                const u64* wc = (const u64*)wc_s;
                u64 a0 = 0, a1 = 0;
#pragma unroll
                for (int k = 0; k < 4; k++) {
                    a0 = fma2(wc[2 * k],     hp[2 * k],     a0);
                    a1 = fma2(wc[2 * k + 1], hp[2 * k + 1], a1);
                }
                crb[t] = hsum2(add2(a0, a1)) + bcr;
            }
        };

        __syncthreads();                     // match producer prologue

        float4 mv4 = make_float4(0.f, 0.f, 0.f, 0.f);

        for (int cc = 0; cc < NCHUNK; cc++) {
            if (cc >= 1) critic_pass(cc - 1);
#pragma unroll
            for (int s = 0; s < CH; s++) {
                const int t = cc * CH + s;
                if ((s & 3) == 0) mv4 = *(const float4*)&mb[t];
                const float m = (s & 3) == 0 ? mv4.x
                              : (s & 3) == 1 ? mv4.y
                              : (s & 3) == 2 ? mv4.z : mv4.w;
                const float cm = c * m;

                u64 hv[8];                   // h_{t-1} broadcast
                {
                    const ulonglong2* hp = (const ulonglong2*)&hbuf[e][(t + 31) & 31][0];
#pragma unroll
                    for (int q = 0; q < 4; q++) {
                        const ulonglong2 v = hp[q];
                        hv[2 * q] = v.x; hv[2 * q + 1] = v.y;
                    }
                }
                // fused actor head for step t-1 (reuses hv)
                {
                    u64 A0 = 0, A1 = 0;
#pragma unroll
                    for (int k = 0; k < 4; k++) {
                        A0 = fma2(wa[2 * k],     hv[2 * k],     A0);
                        A1 = fma2(wa[2 * k + 1], hv[2 * k + 1], A1);
                    }
                    const float av = hsum2(add2(A0, A1)) + bact;
                    if (t > 0) actb[(t - 1) * Asz + lane] = av;
                }
                // gates
                u64 aP0 = 0, aP1 = 0, aQ0 = 0, aQ1 = 0;
#pragma unroll
                for (int k = 0; k < 4; k++) {
                    aP0 = fma2(whP[2 * k],     hv[2 * k],     aP0);
                    aP1 = fma2(whP[2 * k + 1], hv[2 * k + 1], aP1);
                    aQ0 = fma2(whQ[2 * k],     hv[2 * k],     aQ0);
                    aQ1 = fma2(whQ[2 * k + 1], hv[2 * k + 1], aQ1);
                }
                const float sP = hsum2(add2(aP0, aP1));
                const float sQ = hsum2(add2(aQ0, aQ1));

                const float2 pgv = *(const float2*)&pgsm[e][cc & 1][s * 64 + 2 * lane];

                const float gP = fmaf(m, sP, pgv.x);   // lo: i, hi: f
                const float gQ = fmaf(m, sQ, pgv.y);   // lo: g, hi: o

                const float vP = sigmoid_fast(gP);
                const float tQ = tanh_fast(hi_half ? 0.5f * gQ : gQ);
                const float vQ = hi_half ? fmaf(0.5f, tQ, 0.5f) : tQ;

                const float p  = vP * vQ;                          // lo: i*g
                const float ig = __shfl_sync(0xffffffffu, p, j);   // hi gets i*g

                c  = fmaf(vP, cm, ig);                             // hi lanes
                h2 = vQ * tanh_fast(c);                            // hi lanes

                if (hi_half) hbuf[e][t & 31][j] = h2;
                __syncwarp();
            }
            __syncthreads();
        }
        critic_pass(NCHUNK - 1);

        // tail: actor for t = Tsz-1
        {
            u64 hv[8];
            const ulonglong2* hp = (const ulonglong2*)&hbuf[e][(Tsz - 1) & 31][0];
#pragma unroll
            for (int q = 0; q < 4; q++) {
                const ulonglong2 v = hp[q];
                hv[2 * q] = v.x; hv[2 * q + 1] = v.y;
            }
            u64 A0 = 0, A1 = 0;
#pragma unroll
            for (int k = 0; k < 4; k++) {
                A0 = fma2(wa[2 * k],     hv[2 * k],     A0);
                A1 = fma2(wa[2 * k + 1], hv[2 * k + 1], A1);
            }
            actb[(Tsz - 1) * Asz + lane] = hsum2(add2(A0, A1)) + bact;
        }

        if (hi_half) {
            hT[b * Hsz + j] = h2;
            cT[b * Hsz + j] = c;
        }
    }
}

extern "C" void kernel_launch(void* const* d_in, const int* in_sizes, int n_in,
                              void* d_out, int out_size) {
    const float* xin      = (const float*)d_in[0];
    const float* masks    = (const float*)d_in[1];
    const float* h0       = (const float*)d_in[2];
    const float* c0       = (const float*)d_in[3];
    const float* w_ih     = (const float*)d_in[4];
    const float* w_hh     = (const float*)d_in[5];
    const float* b_ih     = (const float*)d_in[6];
    const float* b_hh     = (const float*)d_in[7];
    const float* w_actor  = (const float*)d_in[8];
    const float* b_actor  = (const float*)d_in[9];
    const float* w_critic = (const float*)d_in[10];
    const float* b_critic = (const float*)d_in[11];

    float* out    = (float*)d_out;
    float* actor  = out;
    float* critic = actor + (size_t)Bsz * Tsz * Asz;
    float* hT     = critic + (size_t)Bsz * Tsz;
    float* cT     = hT + (size_t)Bsz * Hsz;

    lstm_fused<<<Bsz / 4, 192>>>(xin, masks, h0, c0, w_ih, w_hh, b_ih, b_hh,
                                 w_actor, b_actor, w_critic, b_critic,
                                 actor, critic, hT, cT);
}